// round 6
// baseline (speedup 1.0000x reference)
#include <cuda_runtime.h>
#include <math.h>

#define TT 4096
#define BB 128
#define HH 256
#define MAXSEG (BB*(TT/5))
#define PI_F 3.14159265358979323846f

typedef unsigned long long u64;
__device__ __forceinline__ u64 pk2(float lo, float hi){ u64 r; asm("mov.b64 %0,{%1,%2};":"=l"(r):"f"(lo),"f"(hi)); return r; }
__device__ __forceinline__ void up2(u64 v, float& lo, float& hi){ asm("mov.b64 {%0,%1},%2;":"=f"(lo),"=f"(hi):"l"(v)); }
__device__ __forceinline__ void fma2(u64& d, u64 a, u64 b){ asm("fma.rn.f32x2 %0,%1,%2,%0;":"+l"(d):"l"(a),"l"(b)); }
__device__ __forceinline__ unsigned smem_u32(const void* p){
    unsigned a; asm("{ .reg .u64 t; cvta.to.shared.u64 t, %1; cvt.u32.u64 %0, t; }":"=r"(a):"l"(p)); return a;
}
__device__ __forceinline__ u64 dsmem_ld(unsigned saddr, unsigned rank){
    unsigned ra; u64 v;
    asm volatile("mapa.shared::cluster.u32 %0, %1, %2;" : "=r"(ra) : "r"(saddr), "r"(rank));
    asm volatile("ld.shared::cluster.u64 %0, [%1];" : "=l"(v) : "r"(ra));
    return v;
}
__device__ __forceinline__ void cluster_sync_(){
    asm volatile("barrier.cluster.arrive.aligned;" ::: "memory");
    asm volatile("barrier.cluster.wait.aligned;" ::: "memory");
}

// ---------------- scratch ----------------
__device__ float g_rot[(size_t)BB*TT*3];
__device__ float g_ar[(size_t)MAXSEG*HH];
__device__ float g_gx[(size_t)MAXSEG*3*HH];
__device__ int   g_segs[BB], g_rr[BB], g_offs[BB+1];
__device__ float g_ox[BB], g_oy[BB], g_hd[BB], g_c[BB], g_s[BB];
__device__ int   g_total, g_gmax[16];

// ---------------- kernel 0: setup ----------------
__global__ void k_setup(const float* __restrict__ traj, const int* __restrict__ len)
{
    int b = threadIdx.x;
    __shared__ int ss[BB];
    if (b < BB) {
        int L = len[b];
        g_segs[b] = L/5; g_rr[b] = L%5; ss[b] = L/5;
        const float* last = traj + ((size_t)b*TT + (size_t)(L-1))*3;
        g_ox[b]=last[0]; g_oy[b]=last[1]; float hd=-last[2]; g_hd[b]=hd;
        float th = hd*(PI_F/180.0f);
        g_c[b]=cosf(th); g_s[b]=sinf(th);
    }
    __syncthreads();
    if (b == 0) {
        int acc=0;
        for (int i=0;i<BB;i++){ g_offs[i]=acc; acc+=ss[i]; }
        g_offs[BB]=acc; g_total=acc;
        for (int g=0; g<16; g++){
            int mx=0;
            for (int i=0;i<8;i++) if (ss[g*8+i]>mx) mx=ss[g*8+i];
            g_gmax[g]=mx;
        }
    }
}

// ---------------- kernel 1: rotate ----------------
__global__ void k_rot(const float* __restrict__ traj)
{
    int i = blockIdx.x*blockDim.x + threadIdx.x;
    const int tot = BB*TT;
    for (; i<tot; i += gridDim.x*blockDim.x) {
        int b = i >> 12;
        size_t base = (size_t)i*3;
        float x=traj[base], y=traj[base+1], a=traj[base+2];
        float dx=x-g_ox[b], dy=y-g_oy[b], c=g_c[b], s=g_s[b];
        g_rot[base]   = c*dx - s*dy;
        g_rot[base+1] = s*dx + c*dy;
        float aa = fmodf(a + g_hd[b] + 720.0f, 360.0f) * (PI_F/180.0f);
        if (aa > PI_F) aa -= 2.0f*PI_F;
        g_rot[base+2] = aa;
    }
}

// ---------------- kernel 2: conv1+conv2+mean (FFMA2) ----------------
#define OCG 32
#define SEGC 12
#define CTHR 192
#define YSLAB (HH*8+4)
__global__ __launch_bounds__(CTHR,1) void k_conv(const float* __restrict__ w1,
                                                 const float* __restrict__ b1,
                                                 const float* __restrict__ w2,
                                                 const float* __restrict__ b2)
{
    extern __shared__ float sm[];
    float* sW2f = sm;
    float* sY   = sW2f + 768*16*2;
    float* sW1  = sY + SEGC*YSLAB;
    float* sB1  = sW1 + 2304;
    float* sB2  = sB1 + 256;
    float* sR   = sB2 + 32;
    u64* sW2 = (u64*)sW2f;
    __shared__ int sOffs[BB+1];
    __shared__ int sBi[SEGC], sT0[SEGC];

    const int tid = threadIdx.x;
    const int ocb = blockIdx.x * OCG;

    for (int idx=tid; idx<768*16; idx+=CTHR) {
        int k = idx>>4, ocp = idx&15;
        int oc0 = ocb + 2*ocp;
        sW2[idx] = pk2(w2[(size_t)oc0*768 + k], w2[(size_t)(oc0+1)*768 + k]);
    }
    for (int idx=tid; idx<2304; idx+=CTHR) sW1[idx]=w1[idx];
    for (int idx=tid; idx<256;  idx+=CTHR) sB1[idx]=b1[idx];
    if (tid < 16) ((u64*)sB2)[tid] = pk2(b2[ocb+2*tid], b2[ocb+2*tid+1]);
    for (int idx=tid; idx<=BB; idx+=CTHR) sOffs[idx]=g_offs[idx];
    __syncthreads();

    const int total   = g_total;
    const int nchunks = (total + SEGC - 1)/SEGC;

    for (int c = blockIdx.y; c < nchunks; c += gridDim.y) {
        const int base = c*SEGC;
        const int cnt  = min(SEGC, total - base);

        if (tid < cnt) {
            int n = base + tid, lo=0, hi=BB;
            while (hi-lo>1){ int mid=(lo+hi)>>1; if (sOffs[mid]<=n) lo=mid; else hi=mid; }
            sBi[tid]=lo; sT0[tid]=g_rr[lo] + 5*(n - sOffs[lo]);
        }
        __syncthreads();
        if (tid < cnt*15) {
            int s = tid/15, e = tid - s*15;
            sR[s*15+e] = g_rot[((size_t)sBi[s]*TT + (size_t)sT0[s])*3 + e];
        }
        __syncthreads();

        for (int ch=tid; ch<HH; ch+=CTHR) {
            float w[9];
            #pragma unroll
            for (int i=0;i<9;i++) w[i]=sW1[ch*9+i];
            const float bb = sB1[ch];
            for (int s=0; s<cnt; s++) {
                float* yb = sY + s*YSLAB + ch*8;
                yb[0]=0.0f; yb[6]=0.0f; yb[7]=0.0f;
                const float* xr = sR + s*15;
                #pragma unroll
                for (int p=0;p<5;p++) {
                    float acc = bb;
                    #pragma unroll
                    for (int dt=0;dt<3;dt++) {
                        int t = p+dt-1;
                        if (t>=0 && t<5)
                            acc += w[0*3+dt]*xr[t*3+0] + w[1*3+dt]*xr[t*3+1] + w[2*3+dt]*xr[t*3+2];
                    }
                    yb[1+p] = fmaxf(acc, 0.0f);
                }
            }
        }
        __syncthreads();

        {
            const int s   = tid >> 4;
            const int ocp = tid & 15;
            if (s < cnt) {
                u64 bb = ((u64*)sB2)[ocp];
                u64 a0=bb, a1=bb, a2=bb, a3=bb, a4=bb;
                const float* yrow = sY + s*YSLAB;
                #pragma unroll 2
                for (int j=0;j<HH;j++) {
                    const float4* yv = (const float4*)(yrow + (j<<3));
                    float4 ya = yv[0], yb4 = yv[1];
                    const u64* wp = sW2 + j*48 + ocp;
                    u64 w0 = wp[0], w1v = wp[16], w2v = wp[32];
                    u64 d0=pk2(ya.x,ya.x), d1=pk2(ya.y,ya.y), d2=pk2(ya.z,ya.z), d3=pk2(ya.w,ya.w);
                    u64 d4=pk2(yb4.x,yb4.x), d5=pk2(yb4.y,yb4.y), d6=pk2(yb4.z,yb4.z);
                    fma2(a0,w0,d0); fma2(a0,w1v,d1); fma2(a0,w2v,d2);
                    fma2(a1,w0,d1); fma2(a1,w1v,d2); fma2(a1,w2v,d3);
                    fma2(a2,w0,d2); fma2(a2,w1v,d3); fma2(a2,w2v,d4);
                    fma2(a3,w0,d3); fma2(a3,w1v,d4); fma2(a3,w2v,d5);
                    fma2(a4,w0,d4); fma2(a4,w1v,d5); fma2(a4,w2v,d6);
                }
                float l0,h0,l1,h1,l2,h2,l3,h3,l4,h4;
                up2(a0,l0,h0); up2(a1,l1,h1); up2(a2,l2,h2); up2(a3,l3,h3); up2(a4,l4,h4);
                float m0 = (fmaxf(l0,0.f)+fmaxf(l1,0.f)+fmaxf(l2,0.f)+fmaxf(l3,0.f)+fmaxf(l4,0.f))*0.2f;
                float m1 = (fmaxf(h0,0.f)+fmaxf(h1,0.f)+fmaxf(h2,0.f)+fmaxf(h3,0.f)+fmaxf(h4,0.f))*0.2f;
                *(u64*)&g_ar[(size_t)(base+s)*HH + ocb + 2*ocp] = pk2(m0,m1);
            }
        }
        __syncthreads();
    }
}

// ---------------- kernel 3: gx = ar @ W_ih^T + b_ih ----------------
__global__ __launch_bounds__(256) void k_gx(const float* __restrict__ wih,
                                            const float* __restrict__ bih)
{
    __shared__ float As[64*33];
    __shared__ float Bs[64*33];
    const int total = g_total;
    const int m0 = blockIdx.x*64;
    if (m0 >= total) return;
    const int g0 = blockIdx.y*64;
    const int tid = threadIdx.x;
    const int tr = (tid>>4)*4, tc = (tid&15)*4;
    float acc[4][4] = {};
    for (int kc=0; kc<HH; kc+=32) {
        for (int idx=tid; idx<64*32; idx+=256) {
            int r=idx>>5, kk=idx&31; int m=m0+r;
            As[r*33+kk] = (m<total) ? g_ar[(size_t)m*HH + kc + kk] : 0.0f;
        }
        for (int idx=tid; idx<64*32; idx+=256) {
            int g=idx>>5, kk=idx&31;
            Bs[g*33+kk] = wih[(size_t)(g0+g)*HH + kc + kk];
        }
        __syncthreads();
        #pragma unroll
        for (int kk=0; kk<32; kk++) {
            float a[4], bv[4];
            #pragma unroll
            for (int i=0;i<4;i++) a[i]=As[(tr+i)*33+kk];
            #pragma unroll
            for (int j=0;j<4;j++) bv[j]=Bs[(tc+j)*33+kk];
            #pragma unroll
            for (int i=0;i<4;i++)
                #pragma unroll
                for (int j=0;j<4;j++) acc[i][j]+=a[i]*bv[j];
        }
        __syncthreads();
    }
    float bi[4];
    #pragma unroll
    for (int j=0;j<4;j++) bi[j]=bih[g0+tc+j];
    #pragma unroll
    for (int i=0;i<4;i++) {
        int m=m0+tr+i;
        if (m<total)
            #pragma unroll
            for (int j=0;j<4;j++) g_gx[(size_t)m*768 + g0+tc+j] = acc[i][j]+bi[j];
    }
}

// ---------------- kernel 4: GRU — cluster(8) DSMEM, h fully on-chip -----------
// grid = 128 blocks x 128 thr; cluster = 8 unit-blocks (32 units each) covering
// one sample-group of 8 samples (4 FFMA2 pairs). One cluster.sync per step.
__global__ __launch_bounds__(128,1) __cluster_dims__(8,1,1)
void k_gru(const float* __restrict__ whh, const float* __restrict__ bhh,
           float* __restrict__ out)
{
    extern __shared__ u64 smu[];
    u64* sWd = smu;                    // 3*256*32 = 24576 : [(gate*256+kk)*32 + uu], dup pairs
    u64* sh  = smu + 24576;            // 4*260 : assembled h [sp][unit]
    u64* sX  = smu + 24576 + 4*260;    // 2*128 : double-buffered own slice [buf][sp*32+uu]

    const int tid  = threadIdx.x;
    const int ug   = blockIdx.x & 7;       // cluster rank = unit block
    const int sg   = blockIdx.x >> 3;      // sample group (8 samples)

    for (int idx=tid; idx<3*256*32; idx+=128) {
        int uu = idx & 31, gk = idx >> 5;
        int gate = gk >> 8, kk = gk & 255;
        float w = whh[(size_t)(gate*HH + ug*32 + uu)*HH + kk];
        sWd[idx] = pk2(w,w);
    }

    const int wrp  = tid >> 5, lane = tid & 31;
    const int uu   = wrp*8 + (lane & 7);
    const int sp   = lane >> 3;
    const int u    = ug*32 + uu;
    const int gp   = sg*4 + sp;
    const int b0   = 2*gp, b1v = b0+1;
    const int seg0 = g_segs[b0], seg1 = g_segs[b1v];
    const int off0 = g_offs[b0], off1 = g_offs[b1v];
    const int kmax = g_gmax[sg];
    const float bhr = bhh[u], bhz = bhh[HH+u], bhn = bhh[2*HH+u];

    sX[sp*32 + uu] = 0ull;                 // h0 = 0 (buffer 0)
    __syncthreads();
    cluster_sync_();                       // all clusters' sX[0] visible

    const unsigned sx_u32 = smem_u32(sX);

    for (int k=0; k<kmax; k++) {
        const int b = k & 1;

        // assemble full h for this group's 4 pairs from the 8 ranks' slices
        {
            unsigned src = sx_u32 + (unsigned)(b*128 + tid)*8u;
            u64* dst = sh + (tid>>5)*260 + (tid&31);
            #pragma unroll
            for (int r=0; r<8; r++) dst[r*32] = dsmem_ld(src, (unsigned)r);
        }
        __syncthreads();

        // gx prefetch (DRAM latency hidden under the FMA loop)
        const int v0 = (k<seg0), v1 = (k<seg1);
        const size_t r0 = (size_t)(off0 + (v0 ? k : 0));
        const size_t r1 = (size_t)(off1 + (v1 ? k : 0));
        float gxr0=__ldg(&g_gx[r0*768+u]), gxz0=__ldg(&g_gx[r0*768+HH+u]), gxn0=__ldg(&g_gx[r0*768+2*HH+u]);
        float gxr1=__ldg(&g_gx[r1*768+u]), gxz1=__ldg(&g_gx[r1*768+HH+u]), gxn1=__ldg(&g_gx[r1*768+2*HH+u]);

        u64 ar=0ull, az=0ull, an=0ull;
        const u64* hp = sh + sp*260;
        #pragma unroll 4
        for (int kk=0; kk<HH; kk++) {
            u64 h = hp[kk];
            fma2(ar, sWd[(kk<<5)        + uu], h);
            fma2(az, sWd[((256+kk)<<5)  + uu], h);
            fma2(an, sWd[((512+kk)<<5)  + uu], h);
        }

        float ar0,ar1,az0,az1,an0,an1, h0old,h1old;
        up2(ar,ar0,ar1); up2(az,az0,az1); up2(an,an0,an1);
        up2(hp[u], h0old, h1old);

        float hn0, hn1;
        if (v0) {
            float r = 1.0f/(1.0f+expf(-(gxr0+ar0+bhr)));
            float z = 1.0f/(1.0f+expf(-(gxz0+az0+bhz)));
            float n = tanhf(gxn0 + r*(an0+bhn));
            hn0 = (1.0f-z)*n + z*h0old;
            out[r0*HH+u] = hn0;
        } else hn0 = h0old;
        if (v1) {
            float r = 1.0f/(1.0f+expf(-(gxr1+ar1+bhr)));
            float z = 1.0f/(1.0f+expf(-(gxz1+az1+bhz)));
            float n = tanhf(gxn1 + r*(an1+bhn));
            hn1 = (1.0f-z)*n + z*h1old;
            out[r1*HH+u] = hn1;
        } else hn1 = h1old;

        sX[(b^1)*128 + sp*32 + uu] = pk2(hn0,hn1);
        cluster_sync_();                   // release new slice; separates peers' reads of sX[b]
    }
}

// ---------------- launch ----------------
extern "C" void kernel_launch(void* const* d_in, const int* in_sizes, int n_in,
                              void* d_out, int out_size)
{
    const float* traj = (const float*)d_in[0];
    const int*   len  = (const int*)  d_in[1];
    const float* c1w  = (const float*)d_in[2];
    const float* c1b  = (const float*)d_in[3];
    const float* c2w  = (const float*)d_in[4];
    const float* c2b  = (const float*)d_in[5];
    const float* wih  = (const float*)d_in[6];
    const float* whh  = (const float*)d_in[7];
    const float* bih  = (const float*)d_in[8];
    const float* bhh  = (const float*)d_in[9];
    float* out = (float*)d_out;

    const int conv_smem = (768*16*2 + SEGC*YSLAB + 2304 + 256 + 32 + 180)*4;
    const int gru_smem  = (24576 + 4*260 + 2*128)*8;     // 206,976 B
    cudaFuncSetAttribute(k_conv, cudaFuncAttributeMaxDynamicSharedMemorySize, conv_smem);
    cudaFuncSetAttribute(k_gru,  cudaFuncAttributeMaxDynamicSharedMemorySize, gru_smem);

    k_setup<<<1, 128>>>(traj, len);
    k_rot<<<512, 256>>>(traj);
    k_conv<<<dim3(8, 18), CTHR, conv_smem>>>(c1w, c1b, c2w, c2b);
    k_gx<<<dim3((MAXSEG + 63)/64, 12), 256>>>(wih, bih);
    k_gru<<<128, 128, gru_smem>>>(whh, bhh, out);
}

// round 7
// speedup vs baseline: 1.6510x; 1.6510x over previous
#include <cuda_runtime.h>
#include <math.h>

#define TT 4096
#define BB 128
#define HH 256
#define MAXSEG (BB*(TT/5))
#define PI_F 3.14159265358979323846f

typedef unsigned long long u64;
__device__ __forceinline__ u64 pk2(float lo, float hi){ u64 r; asm("mov.b64 %0,{%1,%2};":"=l"(r):"f"(lo),"f"(hi)); return r; }
__device__ __forceinline__ void up2(u64 v, float& lo, float& hi){ asm("mov.b64 {%0,%1},%2;":"=f"(lo),"=f"(hi):"l"(v)); }
__device__ __forceinline__ void fma2(u64& d, u64 a, u64 b){ asm("fma.rn.f32x2 %0,%1,%2,%0;":"+l"(d):"l"(a),"l"(b)); }

// ---------------- scratch ----------------
__device__ float g_rot[(size_t)BB*TT*3];
__device__ float g_ar[(size_t)MAXSEG*HH];
__device__ float g_gx[(size_t)MAXSEG*3*HH];
__device__ float g_hs[2][BB*HH];
__device__ int   g_segs[BB], g_rr[BB], g_offs[BB+1];
__device__ float g_ox[BB], g_oy[BB], g_hd[BB], g_c[BB], g_s[BB];
__device__ int   g_total, g_gmax[16];
__device__ unsigned g_barA[16*32], g_barR[16*32];

// ---------------- kernel 0: setup ----------------
__global__ void k_setup(const float* __restrict__ traj, const int* __restrict__ len)
{
    int b = threadIdx.x;
    __shared__ int ss[BB];
    if (b < BB) {
        int L = len[b];
        g_segs[b] = L/5; g_rr[b] = L%5; ss[b] = L/5;
        const float* last = traj + ((size_t)b*TT + (size_t)(L-1))*3;
        g_ox[b]=last[0]; g_oy[b]=last[1]; float hd=-last[2]; g_hd[b]=hd;
        float th = hd*(PI_F/180.0f);
        g_c[b]=cosf(th); g_s[b]=sinf(th);
    }
    __syncthreads();
    if (b == 0) {
        int acc=0;
        for (int i=0;i<BB;i++){ g_offs[i]=acc; acc+=ss[i]; }
        g_offs[BB]=acc; g_total=acc;
        for (int g=0; g<16; g++){
            int mx=0;
            for (int i=0;i<8;i++) if (ss[g*8+i]>mx) mx=ss[g*8+i];
            g_gmax[g]=mx;
        }
    }
    for (int i=b; i<BB*HH; i+=blockDim.x) { g_hs[0][i]=0.0f; g_hs[1][i]=0.0f; }
}

// ---------------- dummy (ncu slot alignment) ----------------
__global__ void k_dummy() {}

// ---------------- kernel 1: rotate ----------------
__global__ void k_rot(const float* __restrict__ traj)
{
    int i = blockIdx.x*blockDim.x + threadIdx.x;
    const int tot = BB*TT;
    for (; i<tot; i += gridDim.x*blockDim.x) {
        int b = i >> 12;
        size_t base = (size_t)i*3;
        float x=traj[base], y=traj[base+1], a=traj[base+2];
        float dx=x-g_ox[b], dy=y-g_oy[b], c=g_c[b], s=g_s[b];
        g_rot[base]   = c*dx - s*dy;
        g_rot[base+1] = s*dx + c*dy;
        float aa = fmodf(a + g_hd[b] + 720.0f, 360.0f) * (PI_F/180.0f);
        if (aa > PI_F) aa -= 2.0f*PI_F;
        g_rot[base+2] = aa;
    }
}

// ---------------- kernel 2: conv1+conv2+mean (FFMA2) ----------------
#define OCG 32
#define SEGC 12
#define CTHR 192
#define YSLAB (HH*8+4)
__global__ __launch_bounds__(CTHR,1) void k_conv(const float* __restrict__ w1,
                                                 const float* __restrict__ b1,
                                                 const float* __restrict__ w2,
                                                 const float* __restrict__ b2)
{
    extern __shared__ float sm[];
    float* sW2f = sm;
    float* sY   = sW2f + 768*16*2;
    float* sW1  = sY + SEGC*YSLAB;
    float* sB1  = sW1 + 2304;
    float* sB2  = sB1 + 256;
    float* sR   = sB2 + 32;
    u64* sW2 = (u64*)sW2f;
    __shared__ int sOffs[BB+1];
    __shared__ int sBi[SEGC], sT0[SEGC];

    const int tid = threadIdx.x;
    const int ocb = blockIdx.x * OCG;

    for (int idx=tid; idx<768*16; idx+=CTHR) {
        int k = idx>>4, ocp = idx&15;
        int oc0 = ocb + 2*ocp;
        sW2[idx] = pk2(w2[(size_t)oc0*768 + k], w2[(size_t)(oc0+1)*768 + k]);
    }
    for (int idx=tid; idx<2304; idx+=CTHR) sW1[idx]=w1[idx];
    for (int idx=tid; idx<256;  idx+=CTHR) sB1[idx]=b1[idx];
    if (tid < 16) ((u64*)sB2)[tid] = pk2(b2[ocb+2*tid], b2[ocb+2*tid+1]);
    for (int idx=tid; idx<=BB; idx+=CTHR) sOffs[idx]=g_offs[idx];
    __syncthreads();

    const int total   = g_total;
    const int nchunks = (total + SEGC - 1)/SEGC;

    for (int c = blockIdx.y; c < nchunks; c += gridDim.y) {
        const int base = c*SEGC;
        const int cnt  = min(SEGC, total - base);

        if (tid < cnt) {
            int n = base + tid, lo=0, hi=BB;
            while (hi-lo>1){ int mid=(lo+hi)>>1; if (sOffs[mid]<=n) lo=mid; else hi=mid; }
            sBi[tid]=lo; sT0[tid]=g_rr[lo] + 5*(n - sOffs[lo]);
        }
        __syncthreads();
        if (tid < cnt*15) {
            int s = tid/15, e = tid - s*15;
            sR[s*15+e] = g_rot[((size_t)sBi[s]*TT + (size_t)sT0[s])*3 + e];
        }
        __syncthreads();

        for (int ch=tid; ch<HH; ch+=CTHR) {
            float w[9];
            #pragma unroll
            for (int i=0;i<9;i++) w[i]=sW1[ch*9+i];
            const float bb = sB1[ch];
            for (int s=0; s<cnt; s++) {
                float* yb = sY + s*YSLAB + ch*8;
                yb[0]=0.0f; yb[6]=0.0f; yb[7]=0.0f;
                const float* xr = sR + s*15;
                #pragma unroll
                for (int p=0;p<5;p++) {
                    float acc = bb;
                    #pragma unroll
                    for (int dt=0;dt<3;dt++) {
                        int t = p+dt-1;
                        if (t>=0 && t<5)
                            acc += w[0*3+dt]*xr[t*3+0] + w[1*3+dt]*xr[t*3+1] + w[2*3+dt]*xr[t*3+2];
                    }
                    yb[1+p] = fmaxf(acc, 0.0f);
                }
            }
        }
        __syncthreads();

        {
            const int s   = tid >> 4;
            const int ocp = tid & 15;
            if (s < cnt) {
                u64 bb = ((u64*)sB2)[ocp];
                u64 a0=bb, a1=bb, a2=bb, a3=bb, a4=bb;
                const float* yrow = sY + s*YSLAB;
                #pragma unroll 2
                for (int j=0;j<HH;j++) {
                    const float4* yv = (const float4*)(yrow + (j<<3));
                    float4 ya = yv[0], yb4 = yv[1];
                    const u64* wp = sW2 + j*48 + ocp;
                    u64 w0 = wp[0], w1v = wp[16], w2v = wp[32];
                    u64 d0=pk2(ya.x,ya.x), d1=pk2(ya.y,ya.y), d2=pk2(ya.z,ya.z), d3=pk2(ya.w,ya.w);
                    u64 d4=pk2(yb4.x,yb4.x), d5=pk2(yb4.y,yb4.y), d6=pk2(yb4.z,yb4.z);
                    fma2(a0,w0,d0); fma2(a0,w1v,d1); fma2(a0,w2v,d2);
                    fma2(a1,w0,d1); fma2(a1,w1v,d2); fma2(a1,w2v,d3);
                    fma2(a2,w0,d2); fma2(a2,w1v,d3); fma2(a2,w2v,d4);
                    fma2(a3,w0,d3); fma2(a3,w1v,d4); fma2(a3,w2v,d5);
                    fma2(a4,w0,d4); fma2(a4,w1v,d5); fma2(a4,w2v,d6);
                }
                float l0,h0,l1,h1,l2,h2,l3,h3,l4,h4;
                up2(a0,l0,h0); up2(a1,l1,h1); up2(a2,l2,h2); up2(a3,l3,h3); up2(a4,l4,h4);
                float m0 = (fmaxf(l0,0.f)+fmaxf(l1,0.f)+fmaxf(l2,0.f)+fmaxf(l3,0.f)+fmaxf(l4,0.f))*0.2f;
                float m1 = (fmaxf(h0,0.f)+fmaxf(h1,0.f)+fmaxf(h2,0.f)+fmaxf(h3,0.f)+fmaxf(h4,0.f))*0.2f;
                *(u64*)&g_ar[(size_t)(base+s)*HH + ocb + 2*ocp] = pk2(m0,m1);
            }
        }
        __syncthreads();
    }
}

// ---------------- kernel 3: gx = ar @ W_ih^T + b_ih ----------------
__global__ __launch_bounds__(256) void k_gx(const float* __restrict__ wih,
                                            const float* __restrict__ bih)
{
    __shared__ float As[64*33];
    __shared__ float Bs[64*33];
    const int total = g_total;
    const int m0 = blockIdx.x*64;
    if (m0 >= total) return;
    const int g0 = blockIdx.y*64;
    const int tid = threadIdx.x;
    const int tr = (tid>>4)*4, tc = (tid&15)*4;
    float acc[4][4] = {};
    for (int kc=0; kc<HH; kc+=32) {
        for (int idx=tid; idx<64*32; idx+=256) {
            int r=idx>>5, kk=idx&31; int m=m0+r;
            As[r*33+kk] = (m<total) ? g_ar[(size_t)m*HH + kc + kk] : 0.0f;
        }
        for (int idx=tid; idx<64*32; idx+=256) {
            int g=idx>>5, kk=idx&31;
            Bs[g*33+kk] = wih[(size_t)(g0+g)*HH + kc + kk];
        }
        __syncthreads();
        #pragma unroll
        for (int kk=0; kk<32; kk++) {
            float a[4], bv[4];
            #pragma unroll
            for (int i=0;i<4;i++) a[i]=As[(tr+i)*33+kk];
            #pragma unroll
            for (int j=0;j<4;j++) bv[j]=Bs[(tc+j)*33+kk];
            #pragma unroll
            for (int i=0;i<4;i++)
                #pragma unroll
                for (int j=0;j<4;j++) acc[i][j]+=a[i]*bv[j];
        }
        __syncthreads();
    }
    float bi[4];
    #pragma unroll
    for (int j=0;j<4;j++) bi[j]=bih[g0+tc+j];
    #pragma unroll
    for (int i=0;i<4;i++) {
        int m=m0+tr+i;
        if (m<total)
            #pragma unroll
            for (int j=0;j<4;j++) g_gx[(size_t)m*768 + g0+tc+j] = acc[i][j]+bi[j];
    }
}

// ---------------- kernel 4: GRU — register-resident weights ----------------
// 128 blocks = 16 sample-groups x 8 unit-blocks (32 units). 256 threads:
// thread = (up = unit-pair 0..15, kh = kk-sixteenth 0..15), covers all 8 samples.
__global__ __launch_bounds__(256,1) void k_gru(const float* __restrict__ whh,
                                               const float* __restrict__ bhh,
                                               float* __restrict__ out)
{
    extern __shared__ u64 smu[];
    u64* shd  = smu;           // 8*260 : dup h per sample
    u64* sred = smu + 8*260;   // 16*8*3*16 = 6144 : kh partials

    const int tid = threadIdx.x;
    const int sg  = blockIdx.x >> 3;
    const int ub  = blockIdx.x & 7;
    const int up  = tid & 15;
    const int kh  = tid >> 4;
    const int u0  = ub*32 + 2*up;

    // register-resident weight slice: 3 gates x 16 kk, unit pair (u0,u0+1)
    u64 wreg[3][16];
    #pragma unroll
    for (int g=0; g<3; g++)
        #pragma unroll
        for (int kk=0; kk<16; kk++) {
            int K = kh*16 + kk;
            wreg[g][kk] = pk2(whh[(size_t)(g*HH+u0)*HH + K],
                              whh[(size_t)(g*HH+u0+1)*HH + K]);
        }

    const int kmax = g_gmax[sg];
    unsigned* barA = &g_barA[sg*32];
    unsigned* barR = &g_barR[sg*32];

    // epilogue role (tid<128): sample esp, unit pair eup
    const int esp = (tid >> 4) & 7;
    const int eup = tid & 15;
    const int eu0 = ub*32 + 2*eup;
    int esegs=0, eoff=0, eb=0;
    float bh0=0,bh1=0,bh2=0,bh3=0,bh4=0,bh5=0;
    if (tid < 128) {
        eb = sg*8 + esp;
        esegs = g_segs[eb]; eoff = g_offs[eb];
        bh0=bhh[eu0];      bh1=bhh[eu0+1];
        bh2=bhh[HH+eu0];   bh3=bhh[HH+eu0+1];
        bh4=bhh[2*HH+eu0]; bh5=bhh[2*HH+eu0+1];
    }
    const u64 ONE = pk2(1.0f, 1.0f);

    for (int k=0; k<kmax; k++) {
        const int cur = k&1, nxt = cur^1;

        // 8-block group barrier
        __syncthreads();
        if (tid==0) {
            __threadfence();
            unsigned t = atomicAdd(barA, 1u);
            unsigned gen = t/8u + 1u;
            if ((t & 7u) == 7u) atomicExch(barR, gen);
            else while (*(volatile unsigned*)barR < gen) { }
        }
        __syncthreads();

        // stage dup'd h for the group's 8 samples
        for (int idx=tid; idx<8*HH; idx+=256) {
            int sp = idx>>8, kk = idx&255;
            float v = __ldcg(&g_hs[cur][(sg*8+sp)*HH + kk]);
            shd[sp*260+kk] = pk2(v,v);
        }
        __syncthreads();

        // gx prefetch (epilogue threads)
        float2 gxr, gxz, gxn; int val=0; size_t row=0;
        if (tid < 128) {
            val = (k < esegs);
            row = (size_t)(eoff + (val ? k : 0));
            gxr = *(const float2*)&g_gx[row*768 + eu0];
            gxz = *(const float2*)&g_gx[row*768 + HH + eu0];
            gxn = *(const float2*)&g_gx[row*768 + 2*HH + eu0];
        }

        // matvec partials: all weights from registers, h from smem
        u64 acc[8][3];
        #pragma unroll
        for (int s=0;s<8;s++){ acc[s][0]=0ull; acc[s][1]=0ull; acc[s][2]=0ull; }
        const int kk0 = kh*16;
        #pragma unroll
        for (int i=0; i<16; i+=2) {
            #pragma unroll
            for (int s=0; s<8; s++) {
                ulonglong2 hh = *(const ulonglong2*)(shd + s*260 + kk0 + i);
                fma2(acc[s][0], wreg[0][i], hh.x); fma2(acc[s][0], wreg[0][i+1], hh.y);
                fma2(acc[s][1], wreg[1][i], hh.x); fma2(acc[s][1], wreg[1][i+1], hh.y);
                fma2(acc[s][2], wreg[2][i], hh.x); fma2(acc[s][2], wreg[2][i+1], hh.y);
            }
        }
        #pragma unroll
        for (int s=0;s<8;s++)
            #pragma unroll
            for (int g=0;g<3;g++)
                sred[(size_t)kh*384 + s*48 + g*16 + up] = acc[s][g];
        __syncthreads();

        if (tid < 128) {
            u64 ar=0ull, az=0ull, an=0ull;
            const u64* rp = sred + esp*48 + eup;
            #pragma unroll
            for (int h2=0; h2<16; h2++) {
                fma2(ar, rp[h2*384],      ONE);
                fma2(az, rp[h2*384 + 16], ONE);
                fma2(an, rp[h2*384 + 32], ONE);
            }
            float arl,arh,azl,azh,anl,anh, hold0,hold1, t0,t1;
            up2(ar,arl,arh); up2(az,azl,azh); up2(an,anl,anh);
            up2(shd[esp*260 + eu0],   hold0, t0);
            up2(shd[esp*260 + eu0+1], hold1, t1);

            float hn0, hn1;
            if (val) {
                float r0 = 1.0f/(1.0f+expf(-(gxr.x+arl+bh0)));
                float r1 = 1.0f/(1.0f+expf(-(gxr.y+arh+bh1)));
                float z0 = 1.0f/(1.0f+expf(-(gxz.x+azl+bh2)));
                float z1 = 1.0f/(1.0f+expf(-(gxz.y+azh+bh3)));
                float n0 = tanhf(gxn.x + r0*(anl+bh4));
                float n1 = tanhf(gxn.y + r1*(anh+bh5));
                hn0 = (1.0f-z0)*n0 + z0*hold0;
                hn1 = (1.0f-z1)*n1 + z1*hold1;
                *(float2*)&out[row*HH + eu0] = make_float2(hn0, hn1);
            } else { hn0 = hold0; hn1 = hold1; }
            __stcg((float2*)&g_hs[nxt][eb*HH + eu0], make_float2(hn0, hn1));
        }
    }
}

// ---------------- launch ----------------
extern "C" void kernel_launch(void* const* d_in, const int* in_sizes, int n_in,
                              void* d_out, int out_size)
{
    const float* traj = (const float*)d_in[0];
    const int*   len  = (const int*)  d_in[1];
    const float* c1w  = (const float*)d_in[2];
    const float* c1b  = (const float*)d_in[3];
    const float* c2w  = (const float*)d_in[4];
    const float* c2b  = (const float*)d_in[5];
    const float* wih  = (const float*)d_in[6];
    const float* whh  = (const float*)d_in[7];
    const float* bih  = (const float*)d_in[8];
    const float* bhh  = (const float*)d_in[9];
    float* out = (float*)d_out;

    const int conv_smem = (768*16*2 + SEGC*YSLAB + 2304 + 256 + 32 + 180)*4;
    const int gru_smem  = (8*260 + 6144)*8;
    cudaFuncSetAttribute(k_conv, cudaFuncAttributeMaxDynamicSharedMemorySize, conv_smem);
    cudaFuncSetAttribute(k_gru,  cudaFuncAttributeMaxDynamicSharedMemorySize, gru_smem);

    k_setup<<<1, 128>>>(traj, len);
    k_rot<<<512, 256>>>(traj);
    k_dummy<<<1, 32>>>();                                   // ncu slot -> k_conv
    k_conv<<<dim3(8, 18), CTHR, conv_smem>>>(c1w, c1b, c2w, c2b);
    k_gx<<<dim3((MAXSEG + 63)/64, 12), 256>>>(wih, bih);
    k_gru<<<128, 256, gru_smem>>>(whh, bhh, out);
}

// round 8
// speedup vs baseline: 2.0378x; 1.2343x over previous
#include <cuda_runtime.h>
#include <math.h>

#define TT 4096
#define BB 128
#define HH 256
#define MAXSEG (BB*(TT/5))
#define PI_F 3.14159265358979323846f

typedef unsigned long long u64;
__device__ __forceinline__ u64 pk2(float lo, float hi){ u64 r; asm("mov.b64 %0,{%1,%2};":"=l"(r):"f"(lo),"f"(hi)); return r; }
__device__ __forceinline__ void up2(u64 v, float& lo, float& hi){ asm("mov.b64 {%0,%1},%2;":"=f"(lo),"=f"(hi):"l"(v)); }
__device__ __forceinline__ void fma2(u64& d, u64 a, u64 b){ asm("fma.rn.f32x2 %0,%1,%2,%0;":"+l"(d):"l"(a),"l"(b)); }

// ---------------- scratch ----------------
__device__ float g_rot[(size_t)BB*TT*3];
__device__ float g_ar[(size_t)MAXSEG*HH];
__device__ float g_gx[(size_t)MAXSEG*3*HH];
__device__ float g_part[(size_t)MAXSEG*5*HH];     // conv2 half-0 partials
__device__ float g_hs[2][BB*HH];
__device__ int   g_segs[BB], g_rr[BB], g_offs[BB+1];
__device__ float g_ox[BB], g_oy[BB], g_hd[BB], g_c[BB], g_s[BB];
__device__ int   g_total, g_gmax[16];
__device__ unsigned g_barA[16*32], g_barR[16*32];

// ---------------- kernel 0: setup ----------------
__global__ void k_setup(const float* __restrict__ traj, const int* __restrict__ len)
{
    int b = threadIdx.x;
    __shared__ int ss[BB];
    if (b < BB) {
        int L = len[b];
        g_segs[b] = L/5; g_rr[b] = L%5; ss[b] = L/5;
        const float* last = traj + ((size_t)b*TT + (size_t)(L-1))*3;
        g_ox[b]=last[0]; g_oy[b]=last[1]; float hd=-last[2]; g_hd[b]=hd;
        float th = hd*(PI_F/180.0f);
        g_c[b]=cosf(th); g_s[b]=sinf(th);
    }
    __syncthreads();
    if (b == 0) {
        int acc=0;
        for (int i=0;i<BB;i++){ g_offs[i]=acc; acc+=ss[i]; }
        g_offs[BB]=acc; g_total=acc;
        for (int g=0; g<16; g++){
            int mx=0;
            for (int i=0;i<8;i++) if (ss[g*8+i]>mx) mx=ss[g*8+i];
            g_gmax[g]=mx;
        }
    }
    for (int i=b; i<BB*HH; i+=blockDim.x) { g_hs[0][i]=0.0f; g_hs[1][i]=0.0f; }
}

// ---------------- kernel 1: rotate ----------------
__global__ void k_rot(const float* __restrict__ traj)
{
    int i = blockIdx.x*blockDim.x + threadIdx.x;
    const int tot = BB*TT;
    for (; i<tot; i += gridDim.x*blockDim.x) {
        int b = i >> 12;
        size_t base = (size_t)i*3;
        float x=traj[base], y=traj[base+1], a=traj[base+2];
        float dx=x-g_ox[b], dy=y-g_oy[b], c=g_c[b], s=g_s[b];
        g_rot[base]   = c*dx - s*dy;
        g_rot[base+1] = s*dx + c*dy;
        float aa = fmodf(a + g_hd[b] + 720.0f, 360.0f) * (PI_F/180.0f);
        if (aa > PI_F) aa -= 2.0f*PI_F;
        g_rot[base+2] = aa;
    }
}

// ---------------- kernel 2: conv, K-split halves (2 blocks/SM) ----------------
#define OCG 32
#define SEGC 12
#define CTHR 192
#define CHH 128              /* channels per half */
#define KH  (CHH*3)          /* 384 k per half */
#define YSLAB_H (CHH*8+4)    /* 1028 floats per segment slab */
__global__ __launch_bounds__(CTHR,2) void k_conv(const float* __restrict__ w1,
                                                 const float* __restrict__ b1,
                                                 const float* __restrict__ w2,
                                                 const float* __restrict__ b2,
                                                 int half)
{
    extern __shared__ float sm[];
    float* sW2f = sm;                     // KH*16 u64 = 12288 f
    float* sY   = sW2f + KH*16*2;         // SEGC*1028
    float* sW1  = sY + SEGC*YSLAB_H;      // 1152
    float* sB1  = sW1 + CHH*9;            // 128
    float* sB2  = sB1 + CHH;              // 32
    float* sR   = sB2 + 32;               // 180
    u64* sW2 = (u64*)sW2f;
    __shared__ int sOffs[BB+1];
    __shared__ int sBi[SEGC], sT0[SEGC];

    const int tid = threadIdx.x;
    const int ocb = blockIdx.x * OCG;
    const int ch0 = half * CHH;

    // weights: sW2[k*16+ocp] = (w2[oc0][ch0*3+k], w2[oc0+1][ch0*3+k])
    for (int idx=tid; idx<KH*16; idx+=CTHR) {
        int k = idx>>4, ocp = idx&15;
        int oc0 = ocb + 2*ocp;
        sW2[idx] = pk2(w2[(size_t)oc0*768 + ch0*3 + k],
                       w2[(size_t)(oc0+1)*768 + ch0*3 + k]);
    }
    for (int idx=tid; idx<CHH*9; idx+=CTHR) sW1[idx]=w1[ch0*9 + idx];
    for (int idx=tid; idx<CHH;   idx+=CTHR) sB1[idx]=b1[ch0 + idx];
    if (tid < 16) ((u64*)sB2)[tid] = pk2(b2[ocb+2*tid], b2[ocb+2*tid+1]);
    for (int idx=tid; idx<=BB; idx+=CTHR) sOffs[idx]=g_offs[idx];
    __syncthreads();

    const int total   = g_total;
    const int nchunks = (total + SEGC - 1)/SEGC;

    for (int c = blockIdx.y; c < nchunks; c += gridDim.y) {
        const int base = c*SEGC;
        const int cnt  = min(SEGC, total - base);

        if (tid < cnt) {
            int n = base + tid, lo=0, hi=BB;
            while (hi-lo>1){ int mid=(lo+hi)>>1; if (sOffs[mid]<=n) lo=mid; else hi=mid; }
            sBi[tid]=lo; sT0[tid]=g_rr[lo] + 5*(n - sOffs[lo]);
        }
        __syncthreads();
        if (tid < cnt*15) {
            int s = tid/15, e = tid - s*15;
            sR[s*15+e] = g_rot[((size_t)sBi[s]*TT + (size_t)sT0[s])*3 + e];
        }
        __syncthreads();

        // conv1 (this half's 128 channels)
        for (int ch=tid; ch<CHH; ch+=CTHR) {
            float w[9];
            #pragma unroll
            for (int i=0;i<9;i++) w[i]=sW1[ch*9+i];
            const float bb = sB1[ch];
            for (int s=0; s<cnt; s++) {
                float* yb = sY + s*YSLAB_H + ch*8;
                yb[0]=0.0f; yb[6]=0.0f; yb[7]=0.0f;
                const float* xr = sR + s*15;
                #pragma unroll
                for (int p=0;p<5;p++) {
                    float acc = bb;
                    #pragma unroll
                    for (int dt=0;dt<3;dt++) {
                        int t = p+dt-1;
                        if (t>=0 && t<5)
                            acc += w[0*3+dt]*xr[t*3+0] + w[1*3+dt]*xr[t*3+1] + w[2*3+dt]*xr[t*3+2];
                    }
                    yb[1+p] = fmaxf(acc, 0.0f);
                }
            }
        }
        __syncthreads();

        // conv2 half-sum over this half's 128 channels
        {
            const int s   = tid >> 4;
            const int ocp = tid & 15;
            if (s < cnt) {
                u64 a0,a1,a2,a3,a4;
                if (half == 0) { u64 bb = ((u64*)sB2)[ocp]; a0=bb;a1=bb;a2=bb;a3=bb;a4=bb; }
                else           { a0=0ull;a1=0ull;a2=0ull;a3=0ull;a4=0ull; }
                const float* yrow = sY + s*YSLAB_H;
                #pragma unroll 2
                for (int j=0;j<CHH;j++) {
                    const float4* yv = (const float4*)(yrow + (j<<3));
                    float4 ya = yv[0], yb4 = yv[1];
                    const u64* wp = sW2 + j*48 + ocp;
                    u64 w0 = wp[0], w1v = wp[16], w2v = wp[32];
                    u64 d0=pk2(ya.x,ya.x), d1=pk2(ya.y,ya.y), d2=pk2(ya.z,ya.z), d3=pk2(ya.w,ya.w);
                    u64 d4=pk2(yb4.x,yb4.x), d5=pk2(yb4.y,yb4.y), d6=pk2(yb4.z,yb4.z);
                    fma2(a0,w0,d0); fma2(a0,w1v,d1); fma2(a0,w2v,d2);
                    fma2(a1,w0,d1); fma2(a1,w1v,d2); fma2(a1,w2v,d3);
                    fma2(a2,w0,d2); fma2(a2,w1v,d3); fma2(a2,w2v,d4);
                    fma2(a3,w0,d3); fma2(a3,w1v,d4); fma2(a3,w2v,d5);
                    fma2(a4,w0,d4); fma2(a4,w1v,d5); fma2(a4,w2v,d6);
                }
                u64* P = (u64*)&g_part[((size_t)(base+s)*5)*HH + ocb + 2*ocp];
                const int strd = HH/2;  // u64 stride per pos
                if (half == 0) {
                    P[0]=a0; P[strd]=a1; P[2*strd]=a2; P[3*strd]=a3; P[4*strd]=a4;
                } else {
                    float l0,h0,l1,h1,l2,h2,l3,h3,l4,h4, pl,ph;
                    up2(P[0],pl,ph);      up2(a0,l0,h0); l0+=pl; h0+=ph;
                    up2(P[strd],pl,ph);   up2(a1,l1,h1); l1+=pl; h1+=ph;
                    up2(P[2*strd],pl,ph); up2(a2,l2,h2); l2+=pl; h2+=ph;
                    up2(P[3*strd],pl,ph); up2(a3,l3,h3); l3+=pl; h3+=ph;
                    up2(P[4*strd],pl,ph); up2(a4,l4,h4); l4+=pl; h4+=ph;
                    float m0 = (fmaxf(l0,0.f)+fmaxf(l1,0.f)+fmaxf(l2,0.f)+fmaxf(l3,0.f)+fmaxf(l4,0.f))*0.2f;
                    float m1 = (fmaxf(h0,0.f)+fmaxf(h1,0.f)+fmaxf(h2,0.f)+fmaxf(h3,0.f)+fmaxf(h4,0.f))*0.2f;
                    *(u64*)&g_ar[(size_t)(base+s)*HH + ocb + 2*ocp] = pk2(m0,m1);
                }
            }
        }
        __syncthreads();
    }
}

// ---------------- kernel 3: gx GEMM (FFMA2, 64x128 tiles) ----------------
__global__ __launch_bounds__(256) void k_gx(const float* __restrict__ wih,
                                            const float* __restrict__ bih)
{
    __shared__ u64 Asd[64*33];      // dup'd ar rows
    __shared__ u64 Bs[64*33];       // col-pair weights [cp][kk]
    const int total = g_total;
    const int m0 = blockIdx.x*64;
    if (m0 >= total) return;
    const int g0 = blockIdx.y*128;
    const int tid = threadIdx.x;
    const int ty = tid >> 4, tx = tid & 15;
    const int tr = ty*4;
    u64 acc[4][4];
    #pragma unroll
    for (int i=0;i<4;i++)
        #pragma unroll
        for (int j=0;j<4;j++) acc[i][j]=0ull;

    for (int kc=0; kc<HH; kc+=32) {
        for (int idx=tid; idx<64*32; idx+=256) {
            int r=idx>>5, kk=idx&31; int m=m0+r;
            float v = (m<total) ? g_ar[(size_t)m*HH + kc + kk] : 0.0f;
            Asd[r*33+kk] = pk2(v,v);
        }
        for (int idx=tid; idx<64*32; idx+=256) {
            int cp=idx>>5, kk=idx&31;
            Bs[cp*33+kk] = pk2(wih[(size_t)(g0+2*cp)*HH + kc + kk],
                               wih[(size_t)(g0+2*cp+1)*HH + kc + kk]);
        }
        __syncthreads();
        #pragma unroll 4
        for (int kk=0; kk<32; kk++) {
            u64 a[4], b[4];
            #pragma unroll
            for (int i=0;i<4;i++) a[i]=Asd[(tr+i)*33+kk];
            #pragma unroll
            for (int j=0;j<4;j++) b[j]=Bs[(tx+16*j)*33+kk];
            #pragma unroll
            for (int i=0;i<4;i++)
                #pragma unroll
                for (int j=0;j<4;j++) fma2(acc[i][j], a[i], b[j]);
        }
        __syncthreads();
    }
    u64 bi[4];
    #pragma unroll
    for (int j=0;j<4;j++) {
        int cp = tx+16*j;
        bi[j] = pk2(bih[g0+2*cp], bih[g0+2*cp+1]);
    }
    #pragma unroll
    for (int i=0;i<4;i++) {
        int m=m0+tr+i;
        if (m<total) {
            #pragma unroll
            for (int j=0;j<4;j++) {
                u64 v = acc[i][j];
                fma2(v, bi[j], pk2(1.0f,1.0f));
                *(u64*)&g_gx[(size_t)m*768 + g0 + 2*(tx+16*j)] = v;
            }
        }
    }
}

// ---------------- kernel 4: GRU — register-resident weights (R7) --------------
__global__ __launch_bounds__(256,1) void k_gru(const float* __restrict__ whh,
                                               const float* __restrict__ bhh,
                                               float* __restrict__ out)
{
    extern __shared__ u64 smu[];
    u64* shd  = smu;           // 8*260
    u64* sred = smu + 8*260;   // 6144

    const int tid = threadIdx.x;
    const int sg  = blockIdx.x >> 3;
    const int ub  = blockIdx.x & 7;
    const int up  = tid & 15;
    const int kh  = tid >> 4;
    const int u0  = ub*32 + 2*up;

    u64 wreg[3][16];
    #pragma unroll
    for (int g=0; g<3; g++)
        #pragma unroll
        for (int kk=0; kk<16; kk++) {
            int K = kh*16 + kk;
            wreg[g][kk] = pk2(whh[(size_t)(g*HH+u0)*HH + K],
                              whh[(size_t)(g*HH+u0+1)*HH + K]);
        }

    const int kmax = g_gmax[sg];
    unsigned* barA = &g_barA[sg*32];
    unsigned* barR = &g_barR[sg*32];

    const int esp = (tid >> 4) & 7;
    const int eup = tid & 15;
    const int eu0 = ub*32 + 2*eup;
    int esegs=0, eoff=0, eb=0;
    float bh0=0,bh1=0,bh2=0,bh3=0,bh4=0,bh5=0;
    if (tid < 128) {
        eb = sg*8 + esp;
        esegs = g_segs[eb]; eoff = g_offs[eb];
        bh0=bhh[eu0];      bh1=bhh[eu0+1];
        bh2=bhh[HH+eu0];   bh3=bhh[HH+eu0+1];
        bh4=bhh[2*HH+eu0]; bh5=bhh[2*HH+eu0+1];
    }
    const u64 ONE = pk2(1.0f, 1.0f);

    for (int k=0; k<kmax; k++) {
        const int cur = k&1, nxt = cur^1;

        __syncthreads();
        if (tid==0) {
            __threadfence();
            unsigned t = atomicAdd(barA, 1u);
            unsigned gen = t/8u + 1u;
            if ((t & 7u) == 7u) atomicExch(barR, gen);
            else while (*(volatile unsigned*)barR < gen) { }
        }
        __syncthreads();

        for (int idx=tid; idx<8*HH; idx+=256) {
            int sp = idx>>8, kk = idx&255;
            float v = __ldcg(&g_hs[cur][(sg*8+sp)*HH + kk]);
            shd[sp*260+kk] = pk2(v,v);
        }
        __syncthreads();

        float2 gxr, gxz, gxn; int val=0; size_t row=0;
        if (tid < 128) {
            val = (k < esegs);
            row = (size_t)(eoff + (val ? k : 0));
            gxr = *(const float2*)&g_gx[row*768 + eu0];
            gxz = *(const float2*)&g_gx[row*768 + HH + eu0];
            gxn = *(const float2*)&g_gx[row*768 + 2*HH + eu0];
        }

        u64 acc[8][3];
        #pragma unroll
        for (int s=0;s<8;s++){ acc[s][0]=0ull; acc[s][1]=0ull; acc[s][2]=0ull; }
        const int kk0 = kh*16;
        #pragma unroll
        for (int i=0; i<16; i+=2) {
            #pragma unroll
            for (int s=0; s<8; s++) {
                ulonglong2 hh = *(const ulonglong2*)(shd + s*260 + kk0 + i);
                fma2(acc[s][0], wreg[0][i], hh.x); fma2(acc[s][0], wreg[0][i+1], hh.y);
                fma2(acc[s][1], wreg[1][i], hh.x); fma2(acc[s][1], wreg[1][i+1], hh.y);
                fma2(acc[s][2], wreg[2][i], hh.x); fma2(acc[s][2], wreg[2][i+1], hh.y);
            }
        }
        #pragma unroll
        for (int s=0;s<8;s++)
            #pragma unroll
            for (int g=0;g<3;g++)
                sred[(size_t)kh*384 + s*48 + g*16 + up] = acc[s][g];
        __syncthreads();

        if (tid < 128) {
            u64 ar=0ull, az=0ull, an=0ull;
            const u64* rp = sred + esp*48 + eup;
            #pragma unroll
            for (int h2=0; h2<16; h2++) {
                fma2(ar, rp[h2*384],      ONE);
                fma2(az, rp[h2*384 + 16], ONE);
                fma2(an, rp[h2*384 + 32], ONE);
            }
            float arl,arh,azl,azh,anl,anh, hold0,hold1, t0,t1;
            up2(ar,arl,arh); up2(az,azl,azh); up2(an,anl,anh);
            up2(shd[esp*260 + eu0],   hold0, t0);
            up2(shd[esp*260 + eu0+1], hold1, t1);

            float hn0, hn1;
            if (val) {
                float r0 = 1.0f/(1.0f+expf(-(gxr.x+arl+bh0)));
                float r1 = 1.0f/(1.0f+expf(-(gxr.y+arh+bh1)));
                float z0 = 1.0f/(1.0f+expf(-(gxz.x+azl+bh2)));
                float z1 = 1.0f/(1.0f+expf(-(gxz.y+azh+bh3)));
                float n0 = tanhf(gxn.x + r0*(anl+bh4));
                float n1 = tanhf(gxn.y + r1*(anh+bh5));
                hn0 = (1.0f-z0)*n0 + z0*hold0;
                hn1 = (1.0f-z1)*n1 + z1*hold1;
                *(float2*)&out[row*HH + eu0] = make_float2(hn0, hn1);
            } else { hn0 = hold0; hn1 = hold1; }
            __stcg((float2*)&g_hs[nxt][eb*HH + eu0], make_float2(hn0, hn1));
        }
    }
}

// ---------------- launch ----------------
extern "C" void kernel_launch(void* const* d_in, const int* in_sizes, int n_in,
                              void* d_out, int out_size)
{
    const float* traj = (const float*)d_in[0];
    const int*   len  = (const int*)  d_in[1];
    const float* c1w  = (const float*)d_in[2];
    const float* c1b  = (const float*)d_in[3];
    const float* c2w  = (const float*)d_in[4];
    const float* c2b  = (const float*)d_in[5];
    const float* wih  = (const float*)d_in[6];
    const float* whh  = (const float*)d_in[7];
    const float* bih  = (const float*)d_in[8];
    const float* bhh  = (const float*)d_in[9];
    float* out = (float*)d_out;

    const int conv_smem = (KH*16*2 + SEGC*YSLAB_H + CHH*9 + CHH + 32 + 180)*4;
    const int gru_smem  = (8*260 + 6144)*8;
    cudaFuncSetAttribute(k_conv, cudaFuncAttributeMaxDynamicSharedMemorySize, conv_smem);
    cudaFuncSetAttribute(k_gru,  cudaFuncAttributeMaxDynamicSharedMemorySize, gru_smem);

    k_setup<<<1, 128>>>(traj, len);
    k_rot<<<512, 256>>>(traj);
    k_conv<<<dim3(8, 36), CTHR, conv_smem>>>(c1w, c1b, c2w, c2b, 0);
    k_conv<<<dim3(8, 36), CTHR, conv_smem>>>(c1w, c1b, c2w, c2b, 1);   // ncu slot #4
    k_gx<<<dim3((MAXSEG + 63)/64, 6), 256>>>(wih, bih);
    k_gru<<<128, 256, gru_smem>>>(whh, bhh, out);
}